// round 16
// baseline (speedup 1.0000x reference)
#include <cuda_runtime.h>

// Shapes (fixed by the problem)
#define Bb 256
#define Cc 256
#define CH 128
#define NN 196               // H*W = 14*14
#define N4 49                // float4s per channel row
#define EPS 1e-5f

#define K1_GRID 2048         // block = (batch, 32-channel slice)
#define K2_GRID 2048         // block = (batch, 32-channel slice)

// Scratch (__device__ globals; fully overwritten per launch -> replay-safe)
// g_tmp_part[bid][ch]: partial of tmp[b,ch] = (Wv @ ysum[b])[ch] from slice grp.
__device__ float g_tmp_part[K1_GRID * CH];   // 1 MB

// ---------------------------------------------------------------------------
// Math: softmax over a singleton axis == 1 -> attention collapses to the
// spatial sum (Wq, Wk dead):
//   tmp[b]   = Wv @ (sum_n y[b,:,n])
//   zbn[b,o] = BN( Wz[o,:] . tmp[b] );   out = x + bcast(zbn)
// tmp distributes over 32-channel slices -> no cross-block dependency in K1.
// ---------------------------------------------------------------------------

// K1 (proven 512-thr shape): block bid covers rows [bid*32, bid*32+32).
// 16 warps x 2 rows, 4 front-batched LDG.128, then the Wv-slice partial.
__global__ void __launch_bounds__(512)
k1(const float* __restrict__ y, const float* __restrict__ Wv) {
    __shared__ float ys_s[32];
    const int bid  = blockIdx.x;
    const int t    = threadIdx.x;
    const int warp = t >> 5;
    const int lane = t & 31;

    // ---- stream: 2 adjacent rows per warp, 4 front-batched LDG.128 ----
    const int r0 = bid * 32 + warp * 2;
    const float4* p0 = reinterpret_cast<const float4*>(y) + (size_t)r0 * N4;
    const float4* p1 = p0 + N4;

    float4 a0 = p0[lane];
    float4 a1 = (lane < N4 - 32) ? p0[lane + 32] : make_float4(0,0,0,0);
    float4 b0 = p1[lane];
    float4 b1 = (lane < N4 - 32) ? p1[lane + 32] : make_float4(0,0,0,0);

    float s0 = a0.x + a0.y + a0.z + a0.w + a1.x + a1.y + a1.z + a1.w;
    float s1 = b0.x + b0.y + b0.z + b0.w + b1.x + b1.y + b1.z + b1.w;
    #pragma unroll
    for (int o = 16; o; o >>= 1) {
        s0 += __shfl_xor_sync(0xFFFFFFFFu, s0, o);
        s1 += __shfl_xor_sync(0xFFFFFFFFu, s1, o);
    }
    if (lane == 0) { ys_s[warp * 2] = s0; ys_s[warp * 2 + 1] = s1; }
    __syncthreads();

    // ---- partial projection: p[ch] = sum_{j<32} Wv[ch, grp*32+j]*ys_s[j] ----
    {
        const int ch = t >> 2, part = t & 3;
        const int grp = bid & 7;
        const float4* wv4 = reinterpret_cast<const float4*>(Wv)
                          + ch * (Cc / 4) + grp * 8 + part * 2;
        float acc = 0.0f;
        #pragma unroll
        for (int i = 0; i < 2; i++) {
            const float4 w = wv4[i];
            const float* yy = ys_s + (part * 2 + i) * 4;
            acc += w.x * yy[0] + w.y * yy[1] + w.z * yy[2] + w.w * yy[3];
        }
        acc += __shfl_xor_sync(0xFFFFFFFFu, acc, 1);
        acc += __shfl_xor_sync(0xFFFFFFFFu, acc, 2);
        if (part == 0) g_tmp_part[bid * CH + ch] = acc;   // coalesced
    }
}

// K2 (R13 body + forced 6 blocks/SM): block bid = (batch b, slice grp).
// Preamble loads issued first, 8 front-batched x LDG.128 (MLP=8), then
// preamble compute while x is in flight. __launch_bounds__(256,6) caps
// regs at ~42 -> 48 resident warps/SM (was 40 at 48 regs).
__global__ void __launch_bounds__(256, 6)
k2(const float* __restrict__ x,
   const float* __restrict__ Wz,
   const float* __restrict__ bn_w,
   const float* __restrict__ bn_b,
   const float* __restrict__ bn_m,
   const float* __restrict__ bn_v,
   float* __restrict__ out) {
    __shared__ __align__(16) float tmp_s[CH];
    __shared__ float zloc[32];
    const int bid  = blockIdx.x;
    const int t    = threadIdx.x;
    const int warp = t >> 5;
    const int lane = t & 31;

    // ---- 1a) issue preamble loads FIRST ----
    // tmp partials: 128 ch x 2 halves (4 partials each)
    const int chA = t >> 1, half = t & 1;
    const int b   = bid >> 3;
    const float* pp = g_tmp_part + (b * 8 + half * 4) * CH + chA;
    const float q0 = __ldg(pp);
    const float q1 = __ldg(pp + CH);
    const float q2 = __ldg(pp + 2 * CH);
    const float q3 = __ldg(pp + 3 * CH);

    // Wz rows for phase B: 32 ch x 8 parts, 64B/thread contiguous
    const int och = t >> 3, part8 = t & 7;
    const int o   = (bid & 7) * 32 + och;
    const float4* wz4 = reinterpret_cast<const float4*>(Wz)
                      + o * (CH / 4) + part8 * 4;
    const float4 w0 = __ldg(wz4 + 0);
    const float4 w1 = __ldg(wz4 + 1);
    const float4 w2 = __ldg(wz4 + 2);
    const float4 w3 = __ldg(wz4 + 3);

    // ---- 1b) then the 8 x loads (consumed last) ----
    const int lr = warp * 4;                            // local rows lr..lr+3
    const size_t f4base = ((size_t)bid * 32 + lr) * N4;
    const float4* X = reinterpret_cast<const float4*>(x) + f4base;
    float4*       O = reinterpret_cast<float4*>(out) + f4base;
    const bool tail = (lane < N4 - 32);

    float4 a0 = X[0*N4 + lane];
    float4 a1 = X[1*N4 + lane];
    float4 a2 = X[2*N4 + lane];
    float4 a3 = X[3*N4 + lane];
    float4 t0 = tail ? X[0*N4 + lane + 32] : make_float4(0,0,0,0);
    float4 t1 = tail ? X[1*N4 + lane + 32] : make_float4(0,0,0,0);
    float4 t2 = tail ? X[2*N4 + lane + 32] : make_float4(0,0,0,0);
    float4 t3 = tail ? X[3*N4 + lane + 32] : make_float4(0,0,0,0);

    // ---- 2) tmp[b] (fixed-order sum -> deterministic) ----
    {
        float a = (q0 + q1) + (q2 + q3);
        a += __shfl_xor_sync(0xFFFFFFFFu, a, 1);        // combine halves
        if (half == 0) tmp_s[chA] = a;
    }
    __syncthreads();

    // ---- 3) zbn for this block's 32 channels ----
    {
        const float4* tp4 = reinterpret_cast<const float4*>(tmp_s) + part8 * 4;
        const float4 v0 = tp4[0];
        const float4 v1 = tp4[1];
        const float4 v2 = tp4[2];
        const float4 v3 = tp4[3];
        float acc = (w0.x*v0.x + w0.y*v0.y + w0.z*v0.z + w0.w*v0.w)
                  + (w1.x*v1.x + w1.y*v1.y + w1.z*v1.z + w1.w*v1.w)
                  + (w2.x*v2.x + w2.y*v2.y + w2.z*v2.z + w2.w*v2.w)
                  + (w3.x*v3.x + w3.y*v3.y + w3.z*v3.z + w3.w*v3.w);
        acc += __shfl_xor_sync(0xFFFFFFFFu, acc, 1);
        acc += __shfl_xor_sync(0xFFFFFFFFu, acc, 2);
        acc += __shfl_xor_sync(0xFFFFFFFFu, acc, 4);
        if (part8 == 0) {
            const float s = rsqrtf(bn_v[o] + EPS) * bn_w[o];
            zloc[och] = acc * s + bn_b[o] - bn_m[o] * s;
        }
    }
    __syncthreads();

    // ---- 4) add + store (x landed during the preamble compute) ----
    const float z0 = zloc[lr + 0];
    const float z1 = zloc[lr + 1];
    const float z2 = zloc[lr + 2];
    const float z3 = zloc[lr + 3];

    a0.x += z0; a0.y += z0; a0.z += z0; a0.w += z0;
    a1.x += z1; a1.y += z1; a1.z += z1; a1.w += z1;
    a2.x += z2; a2.y += z2; a2.z += z2; a2.w += z2;
    a3.x += z3; a3.y += z3; a3.z += z3; a3.w += z3;
    O[0*N4 + lane] = a0;
    O[1*N4 + lane] = a1;
    O[2*N4 + lane] = a2;
    O[3*N4 + lane] = a3;

    if (tail) {
        t0.x += z0; t0.y += z0; t0.z += z0; t0.w += z0;
        t1.x += z1; t1.y += z1; t1.z += z1; t1.w += z1;
        t2.x += z2; t2.y += z2; t2.z += z2; t2.w += z2;
        t3.x += z3; t3.y += z3; t3.z += z3; t3.w += z3;
        O[0*N4 + lane + 32] = t0;
        O[1*N4 + lane + 32] = t1;
        O[2*N4 + lane + 32] = t2;
        O[3*N4 + lane + 32] = t3;
    }
}

// ---------------------------------------------------------------------------
// Inputs (metadata order):
//  0:x 1:y 2:Wq 3:Wk 4:Wv 5:Wz 6:bn_weight 7:bn_bias 8:bn_mean 9:bn_var
// ---------------------------------------------------------------------------
extern "C" void kernel_launch(void* const* d_in, const int* in_sizes, int n_in,
                              void* d_out, int out_size) {
    const float* x    = (const float*)d_in[0];
    const float* y    = (const float*)d_in[1];
    const float* Wv   = (const float*)d_in[4];
    const float* Wz   = (const float*)d_in[5];
    const float* bn_w = (const float*)d_in[6];
    const float* bn_b = (const float*)d_in[7];
    const float* bn_m = (const float*)d_in[8];
    const float* bn_v = (const float*)d_in[9];
    float* out = (float*)d_out;

    k1<<<K1_GRID, 512>>>(y, Wv);
    k2<<<K2_GRID, 256>>>(x, Wz, bn_w, bn_b, bn_m, bn_v, out);
}

// round 17
// speedup vs baseline: 1.0662x; 1.0662x over previous
#include <cuda_runtime.h>

// Shapes (fixed by the problem)
#define Bb 256
#define Cc 256
#define CH 128
#define NN 196               // H*W = 14*14
#define N4 49                // float4s per channel row
#define EPS 1e-5f

#define K1_YS_BLOCKS 2048    // ysum role: block = (batch, 32-channel slice)
#define K1_PF_BLOCKS 256     // x-prefetch role (L2 warmup)
#define K1_GRID (K1_YS_BLOCKS + K1_PF_BLOCKS)
#define K2_GRID 2048         // block = (batch, 32-channel slice)

// x prefetch geometry: 51,380,224 B / 256 blocks = 200,704 B = 1568 lines
#define PF_BYTES_PER_BLOCK 200704
#define PF_LINES_PER_BLOCK 1568

// Scratch (__device__ globals; fully overwritten per launch -> replay-safe)
// g_tmp_part[bid][ch]: partial of tmp[b,ch] = (Wv @ ysum[b])[ch] from slice grp.
__device__ float g_tmp_part[K1_YS_BLOCKS * CH];   // 1 MB

// ---------------------------------------------------------------------------
// Math: softmax over a singleton axis == 1 -> attention collapses to the
// spatial sum (Wq, Wk dead):
//   tmp[b]   = Wv @ (sum_n y[b,:,n])
//   zbn[b,o] = BN( Wz[o,:] . tmp[b] );   out = x + bcast(zbn)
// tmp distributes over 32-channel slices -> no cross-block dependency in K1.
// ---------------------------------------------------------------------------

// K1: ysum role (proven 512-thr shape; y loads streamed with __ldcs so they
// don't evict x from L2) + x-prefetch role (L2 warmup on idle DRAM bandwidth).
__global__ void __launch_bounds__(512)
k1(const float* __restrict__ y, const float* __restrict__ Wv,
   const float* __restrict__ x) {
    __shared__ float ys_s[32];
    const int bid  = blockIdx.x;
    const int t    = threadIdx.x;
    const int warp = t >> 5;
    const int lane = t & 31;

    if (bid >= K1_YS_BLOCKS) {
        // ---- prefetch role: pull this block's 1568 x-lines into L2 ----
        const char* xb = reinterpret_cast<const char*>(x)
                       + (size_t)(bid - K1_YS_BLOCKS) * PF_BYTES_PER_BLOCK;
        for (int i = t; i < PF_LINES_PER_BLOCK; i += 512) {
            asm volatile("prefetch.global.L2 [%0];"
                         :: "l"(xb + (size_t)i * 128));
        }
        return;
    }

    // ---- ysum role: 2 adjacent rows per warp, 4 front-batched LDG.128 ----
    const int r0 = bid * 32 + warp * 2;
    const float4* p0 = reinterpret_cast<const float4*>(y) + (size_t)r0 * N4;
    const float4* p1 = p0 + N4;

    float4 a0 = __ldcs(&p0[lane]);
    float4 a1 = (lane < N4 - 32) ? __ldcs(&p0[lane + 32]) : make_float4(0,0,0,0);
    float4 b0 = __ldcs(&p1[lane]);
    float4 b1 = (lane < N4 - 32) ? __ldcs(&p1[lane + 32]) : make_float4(0,0,0,0);

    float s0 = a0.x + a0.y + a0.z + a0.w + a1.x + a1.y + a1.z + a1.w;
    float s1 = b0.x + b0.y + b0.z + b0.w + b1.x + b1.y + b1.z + b1.w;
    #pragma unroll
    for (int o = 16; o; o >>= 1) {
        s0 += __shfl_xor_sync(0xFFFFFFFFu, s0, o);
        s1 += __shfl_xor_sync(0xFFFFFFFFu, s1, o);
    }
    if (lane == 0) { ys_s[warp * 2] = s0; ys_s[warp * 2 + 1] = s1; }
    __syncthreads();

    // ---- partial projection: p[ch] = sum_{j<32} Wv[ch, grp*32+j]*ys_s[j] ----
    {
        const int ch = t >> 2, part = t & 3;
        const int grp = bid & 7;
        const float4* wv4 = reinterpret_cast<const float4*>(Wv)
                          + ch * (Cc / 4) + grp * 8 + part * 2;
        float acc = 0.0f;
        #pragma unroll
        for (int i = 0; i < 2; i++) {
            const float4 w = wv4[i];
            const float* yy = ys_s + (part * 2 + i) * 4;
            acc += w.x * yy[0] + w.y * yy[1] + w.z * yy[2] + w.w * yy[3];
        }
        acc += __shfl_xor_sync(0xFFFFFFFFu, acc, 1);
        acc += __shfl_xor_sync(0xFFFFFFFFu, acc, 2);
        if (part == 0) g_tmp_part[bid * CH + ch] = acc;   // coalesced
    }
}

// K2 (R13 body, best measured at 19.9us): preamble loads issued first,
// 8 front-batched x LDG.128 (now largely L2-hits), preamble compute while
// x is in flight, then add + store.
__global__ void __launch_bounds__(256)
k2(const float* __restrict__ x,
   const float* __restrict__ Wz,
   const float* __restrict__ bn_w,
   const float* __restrict__ bn_b,
   const float* __restrict__ bn_m,
   const float* __restrict__ bn_v,
   float* __restrict__ out) {
    __shared__ __align__(16) float tmp_s[CH];
    __shared__ float zloc[32];
    const int bid  = blockIdx.x;
    const int t    = threadIdx.x;
    const int warp = t >> 5;
    const int lane = t & 31;

    // ---- 1a) issue preamble loads FIRST ----
    const int chA = t >> 1, half = t & 1;
    const int b   = bid >> 3;
    const float* pp = g_tmp_part + (b * 8 + half * 4) * CH + chA;
    const float q0 = __ldg(pp);
    const float q1 = __ldg(pp + CH);
    const float q2 = __ldg(pp + 2 * CH);
    const float q3 = __ldg(pp + 3 * CH);

    const int och = t >> 3, part8 = t & 7;
    const int o   = (bid & 7) * 32 + och;
    const float4* wz4 = reinterpret_cast<const float4*>(Wz)
                      + o * (CH / 4) + part8 * 4;
    const float4 w0 = __ldg(wz4 + 0);
    const float4 w1 = __ldg(wz4 + 1);
    const float4 w2 = __ldg(wz4 + 2);
    const float4 w3 = __ldg(wz4 + 3);

    // ---- 1b) then the 8 x loads (L2-warm after k1's prefetch) ----
    const int lr = warp * 4;                            // local rows lr..lr+3
    const size_t f4base = ((size_t)bid * 32 + lr) * N4;
    const float4* X = reinterpret_cast<const float4*>(x) + f4base;
    float4*       O = reinterpret_cast<float4*>(out) + f4base;
    const bool tail = (lane < N4 - 32);

    float4 a0 = X[0*N4 + lane];
    float4 a1 = X[1*N4 + lane];
    float4 a2 = X[2*N4 + lane];
    float4 a3 = X[3*N4 + lane];
    float4 t0 = tail ? X[0*N4 + lane + 32] : make_float4(0,0,0,0);
    float4 t1 = tail ? X[1*N4 + lane + 32] : make_float4(0,0,0,0);
    float4 t2 = tail ? X[2*N4 + lane + 32] : make_float4(0,0,0,0);
    float4 t3 = tail ? X[3*N4 + lane + 32] : make_float4(0,0,0,0);

    // ---- 2) tmp[b] (fixed-order sum -> deterministic) ----
    {
        float a = (q0 + q1) + (q2 + q3);
        a += __shfl_xor_sync(0xFFFFFFFFu, a, 1);        // combine halves
        if (half == 0) tmp_s[chA] = a;
    }
    __syncthreads();

    // ---- 3) zbn for this block's 32 channels ----
    {
        const float4* tp4 = reinterpret_cast<const float4*>(tmp_s) + part8 * 4;
        const float4 v0 = tp4[0];
        const float4 v1 = tp4[1];
        const float4 v2 = tp4[2];
        const float4 v3 = tp4[3];
        float acc = (w0.x*v0.x + w0.y*v0.y + w0.z*v0.z + w0.w*v0.w)
                  + (w1.x*v1.x + w1.y*v1.y + w1.z*v1.z + w1.w*v1.w)
                  + (w2.x*v2.x + w2.y*v2.y + w2.z*v2.z + w2.w*v2.w)
                  + (w3.x*v3.x + w3.y*v3.y + w3.z*v3.z + w3.w*v3.w);
        acc += __shfl_xor_sync(0xFFFFFFFFu, acc, 1);
        acc += __shfl_xor_sync(0xFFFFFFFFu, acc, 2);
        acc += __shfl_xor_sync(0xFFFFFFFFu, acc, 4);
        if (part8 == 0) {
            const float s = rsqrtf(bn_v[o] + EPS) * bn_w[o];
            zloc[och] = acc * s + bn_b[o] - bn_m[o] * s;
        }
    }
    __syncthreads();

    // ---- 4) add + store (x landed during the preamble compute) ----
    const float z0 = zloc[lr + 0];
    const float z1 = zloc[lr + 1];
    const float z2 = zloc[lr + 2];
    const float z3 = zloc[lr + 3];

    a0.x += z0; a0.y += z0; a0.z += z0; a0.w += z0;
    a1.x += z1; a1.y += z1; a1.z += z1; a1.w += z1;
    a2.x += z2; a2.y += z2; a2.z += z2; a2.w += z2;
    a3.x += z3; a3.y += z3; a3.z += z3; a3.w += z3;
    O[0*N4 + lane] = a0;
    O[1*N4 + lane] = a1;
    O[2*N4 + lane] = a2;
    O[3*N4 + lane] = a3;

    if (tail) {
        t0.x += z0; t0.y += z0; t0.z += z0; t0.w += z0;
        t1.x += z1; t1.y += z1; t1.z += z1; t1.w += z1;
        t2.x += z2; t2.y += z2; t2.z += z2; t2.w += z2;
        t3.x += z3; t3.y += z3; t3.z += z3; t3.w += z3;
        O[0*N4 + lane + 32] = t0;
        O[1*N4 + lane + 32] = t1;
        O[2*N4 + lane + 32] = t2;
        O[3*N4 + lane + 32] = t3;
    }
}

// ---------------------------------------------------------------------------
// Inputs (metadata order):
//  0:x 1:y 2:Wq 3:Wk 4:Wv 5:Wz 6:bn_weight 7:bn_bias 8:bn_mean 9:bn_var
// ---------------------------------------------------------------------------
extern "C" void kernel_launch(void* const* d_in, const int* in_sizes, int n_in,
                              void* d_out, int out_size) {
    const float* x    = (const float*)d_in[0];
    const float* y    = (const float*)d_in[1];
    const float* Wv   = (const float*)d_in[4];
    const float* Wz   = (const float*)d_in[5];
    const float* bn_w = (const float*)d_in[6];
    const float* bn_b = (const float*)d_in[7];
    const float* bn_m = (const float*)d_in[8];
    const float* bn_v = (const float*)d_in[9];
    float* out = (float*)d_out;

    k1<<<K1_GRID, 512>>>(y, Wv, x);
    k2<<<K2_GRID, 256>>>(x, Wz, bn_w, bn_b, bn_m, bn_v, out);
}